// round 4
// baseline (speedup 1.0000x reference)
#include <cuda_runtime.h>
#include <cuda_bf16.h>
#include <math.h>

#define BB 8
#define CC 64
#define TT 192
#define FF 128
#define LT 192
#define LF 128
#define CSPLIT_T 8   // 8 channel-splits (time view)
#define CSPLIT_F 16  // 16 channel-splits (freq view)

// ---------------- scratch (device globals; no allocation allowed) ----------------
__device__ float g_GT [2 * BB * LT * LT];
__device__ float g_GF [2 * BB * LF * LF];
__device__ float g_ST [2 * BB * LT * LT];
__device__ float g_LST[2 * BB * LT * LT];
__device__ float g_SF [2 * BB * LF * LF];
__device__ float g_LSF[2 * BB * LF * LF];
__device__ float g_mT [2 * BB * LT];
__device__ float g_mF [2 * BB * LF];
__device__ float g_entT[BB * LT];
__device__ float g_entF[BB * LF];

// ---------------- helpers ----------------
__device__ __forceinline__ float blockReduceSum(float v, float* sh) {
    int tid = threadIdx.x;
    sh[tid] = v; __syncthreads();
    #pragma unroll
    for (int s = 128; s > 0; s >>= 1) {
        if (tid < s) sh[tid] += sh[tid + s];
        __syncthreads();
    }
    float r = sh[0]; __syncthreads();
    return r;
}

__device__ __forceinline__ float blockReduceMax(float v, float* sh) {
    int tid = threadIdx.x;
    sh[tid] = v; __syncthreads();
    #pragma unroll
    for (int s = 128; s > 0; s >>= 1) {
        if (tid < s) sh[tid] = fmaxf(sh[tid], sh[tid + s]);
        __syncthreads();
    }
    float r = sh[0]; __syncthreads();
    return r;
}

// Linear(1,4) + ReLU + LayerNorm(4, eps=1e-5) with affine (g, beta)
__device__ __forceinline__ void mlp4(float x, const float* __restrict__ W,
                                     const float* __restrict__ b,
                                     const float* __restrict__ g,
                                     const float* __restrict__ be, float* o) {
    float h[4];
    float mu = 0.f;
    #pragma unroll
    for (int i = 0; i < 4; ++i) {
        h[i] = fmaxf(fmaf(W[i], x, b[i]), 0.f);
        mu += h[i];
    }
    mu *= 0.25f;
    float var = 0.f;
    #pragma unroll
    for (int i = 0; i < 4; ++i) {
        float d = h[i] - mu;
        var = fmaf(d, d, var);
    }
    var *= 0.25f;
    float inv = rsqrtf(var + 1e-5f);
    #pragma unroll
    for (int i = 0; i < 4; ++i)
        o[i] = fmaf(g[i], (h[i] - mu) * inv, be[i]);
}

// ---------------- gram kernels ----------------
// Time view: G[b,i,j] = sum_{c,f} feat[b,c,i,f] * feat[b,c,j,f], L=192, 3x3 tiles of 64
// Transposed smem layout [k][row] (pad 4 -> 16B-aligned rows) so inner loop is
// 2x LDS.128 (2 phases each) + 16 FMA per kk -> FMA-pipe bound.
__global__ __launch_bounds__(256)
void gram_time_kernel(const float* __restrict__ fs, const float* __restrict__ ft) {
    const int pair = blockIdx.x % 6;
    const int cs   = blockIdx.x / 6;
    const int b    = blockIdx.y;
    const int z    = blockIdx.z;
    const int PI[6] = {0, 0, 0, 1, 1, 2};
    const int PJ[6] = {0, 1, 2, 1, 2, 2};
    const int ti = PI[pair], tj = PJ[pair];
    const float* X = (z == 0 ? fs : ft) + (size_t)b * CC * TT * FF;

    __shared__ __align__(16) float AsT[32][68];  // [k][row]
    __shared__ __align__(16) float BsT[32][68];

    const int tid = threadIdx.x;
    const int tx = tid & 15, ty = tid >> 4;
    float acc[4][4];
    #pragma unroll
    for (int u = 0; u < 4; ++u)
        #pragma unroll
        for (int v = 0; v < 4; ++v) acc[u][v] = 0.f;

    const int cper = CC / CSPLIT_T;
    const int c0 = cs * cper;
    const int lk = tid & 31, lr0 = tid >> 5;

    for (int c = c0; c < c0 + cper; ++c) {
        const float* base = X + (size_t)c * TT * FF;
        for (int f0 = 0; f0 < FF; f0 += 32) {
            #pragma unroll
            for (int it = 0; it < 8; ++it) {
                int r = lr0 + it * 8;
                AsT[lk][r] = base[(ti * 64 + r) * FF + f0 + lk];
                BsT[lk][r] = base[(tj * 64 + r) * FF + f0 + lk];
            }
            __syncthreads();
            #pragma unroll
            for (int kk = 0; kk < 32; ++kk) {
                float4 a4 = *(const float4*)&AsT[kk][ty * 4];
                float4 b4 = *(const float4*)&BsT[kk][tx * 4];
                float a[4]  = {a4.x, a4.y, a4.z, a4.w};
                float bb[4] = {b4.x, b4.y, b4.z, b4.w};
                #pragma unroll
                for (int u = 0; u < 4; ++u)
                    #pragma unroll
                    for (int v = 0; v < 4; ++v)
                        acc[u][v] = fmaf(a[u], bb[v], acc[u][v]);
            }
            __syncthreads();
        }
    }

    float* G = g_GT + ((size_t)z * BB + b) * LT * LT;
    #pragma unroll
    for (int u = 0; u < 4; ++u) {
        int i = ti * 64 + ty * 4 + u;
        #pragma unroll
        for (int v = 0; v < 4; ++v) {
            int j = tj * 64 + tx * 4 + v;
            atomicAdd(&G[i * LT + j], acc[u][v]);
            if (ti != tj) atomicAdd(&G[j * LT + i], acc[u][v]);
        }
    }
}

// Freq view: G[b,f1,f2] = sum_{c,t} feat[b,c,t,f1] * feat[b,c,t,f2], L=128, 2x2 tiles of 64
__global__ __launch_bounds__(256)
void gram_freq_kernel(const float* __restrict__ fs, const float* __restrict__ ft) {
    const int pair = blockIdx.x % 3;
    const int cs   = blockIdx.x / 3;
    const int b    = blockIdx.y;
    const int z    = blockIdx.z;
    const int PI[3] = {0, 0, 1};
    const int PJ[3] = {0, 1, 1};
    const int ti = PI[pair], tj = PJ[pair];
    const float* X = (z == 0 ? fs : ft) + (size_t)b * CC * TT * FF;

    __shared__ __align__(16) float As[32][64];
    __shared__ __align__(16) float Bs[32][64];

    const int tid = threadIdx.x;
    const int tx = tid & 15, ty = tid >> 4;
    float acc[4][4];
    #pragma unroll
    for (int u = 0; u < 4; ++u)
        #pragma unroll
        for (int v = 0; v < 4; ++v) acc[u][v] = 0.f;

    const int cper = CC / CSPLIT_F;
    const int c0 = cs * cper;
    const int lf = tid & 63, lt0 = tid >> 6;

    for (int c = c0; c < c0 + cper; ++c) {
        const float* base = X + (size_t)c * TT * FF;
        for (int t0 = 0; t0 < TT; t0 += 32) {
            #pragma unroll
            for (int it = 0; it < 8; ++it) {
                int kt = lt0 + it * 4;
                As[kt][lf] = base[(t0 + kt) * FF + ti * 64 + lf];
                Bs[kt][lf] = base[(t0 + kt) * FF + tj * 64 + lf];
            }
            __syncthreads();
            #pragma unroll
            for (int kk = 0; kk < 32; ++kk) {
                float4 a4 = *(const float4*)&As[kk][ty * 4];
                float4 b4 = *(const float4*)&Bs[kk][tx * 4];
                float a[4]  = {a4.x, a4.y, a4.z, a4.w};
                float bb[4] = {b4.x, b4.y, b4.z, b4.w};
                #pragma unroll
                for (int u = 0; u < 4; ++u)
                    #pragma unroll
                    for (int v = 0; v < 4; ++v)
                        acc[u][v] = fmaf(a[u], bb[v], acc[u][v]);
            }
            __syncthreads();
        }
    }

    float* G = g_GF + ((size_t)z * BB + b) * LF * LF;
    #pragma unroll
    for (int u = 0; u < 4; ++u) {
        int i = ti * 64 + ty * 4 + u;
        #pragma unroll
        for (int v = 0; v < 4; ++v) {
            int j = tj * 64 + tx * 4 + v;
            atomicAdd(&G[i * LF + j], acc[u][v]);
            if (ti != tj) atomicAdd(&G[j * LF + i], acc[u][v]);
        }
    }
}

// ---------------- postprocess: P, row-mean, row-softmax(+EPS), log(+EPS), entropy ----------------
__global__ __launch_bounds__(256)
void postproc_kernel(const float* __restrict__ Gall, float* __restrict__ Sall,
                     float* __restrict__ LSall, float* __restrict__ mall,
                     float* __restrict__ entall, int L) {
    const int row = blockIdx.x, b = blockIdx.y, z = blockIdx.z;
    const float* G = Gall + ((size_t)z * BB + b) * L * L;
    __shared__ float red[256];
    const int j = threadIdx.x;
    const bool act = j < L;

    float P = 0.f;
    if (act) {
        float invn_j = 1.f / fmaxf(sqrtf(G[(size_t)j * L + j]), 1e-8f);
        float invn_i = 1.f / fmaxf(sqrtf(G[(size_t)row * L + row]), 1e-8f);
        P = fmaf(G[(size_t)row * L + j] * invn_i * invn_j, 0.5f, 0.5f);
    }
    float msum = blockReduceSum(act ? P : 0.f, red);
    if (j == 0) mall[((size_t)z * BB + b) * L + row] = msum / (float)L;

    float mx = blockReduceMax(act ? P : -3.4e38f, red);
    float e = act ? expf(P - mx) : 0.f;
    float es = blockReduceSum(e, red);
    float S  = e / es + 1e-8f;
    float LSv = logf(S + 1e-8f);
    if (act) {
        size_t o = ((size_t)z * BB + b) * L * L + (size_t)row * L + j;
        Sall[o]  = S;
        LSall[o] = LSv;
    }
    if (z == 1) {
        float ev = blockReduceSum(act ? S * LSv : 0.f, red);
        if (j == 0) entall[(size_t)b * L + row] = ev;
    }
}

// ---------------- alpha + KL + loss reduction ----------------
__global__ __launch_bounds__(256)
void loss_kernel(const float* __restrict__ Sall, const float* __restrict__ LSall,
                 const float* __restrict__ mall, const float* __restrict__ entall,
                 const float* __restrict__ Wq, const float* __restrict__ bq,
                 const float* __restrict__ gq, const float* __restrict__ Bq,
                 const float* __restrict__ Wk, const float* __restrict__ bk,
                 const float* __restrict__ gk, const float* __restrict__ Bk,
                 float* __restrict__ out, int L, float inv_denom) {
    const int s = blockIdx.x, b = blockIdx.y;
    __shared__ float red[256];
    __shared__ float kv[192 * 4];
    __shared__ float alpha[192];
    __shared__ float lsrow[192];
    const int tid = threadIdx.x;
    const bool act = tid < L;

    const float* m_s = mall + (size_t)b * L;            // z = 0 (source)
    const float* m_t = mall + ((size_t)BB + b) * L;     // z = 1 (target)

    if (act) {
        float kk4[4];
        mlp4(m_t[tid], Wk, bk, gk, Bk, kk4);
        #pragma unroll
        for (int h = 0; h < 4; ++h) kv[tid * 4 + h] = kk4[h];
        lsrow[tid] = LSall[(size_t)b * L * L + (size_t)s * L + tid];
    }
    float q[4];
    mlp4(m_s[s], Wq, bq, gq, Bq, q);
    __syncthreads();

    const float inv_scale = 1.f / sqrtf(4.0f + 1e-8f);
    float logit = -3.4e38f;
    if (act) {
        float d = q[0] * kv[tid * 4 + 0] + q[1] * kv[tid * 4 + 1] +
                  q[2] * kv[tid * 4 + 2] + q[3] * kv[tid * 4 + 3];
        logit = d * inv_scale;
    }
    float mx = blockReduceMax(logit, red);
    float e = act ? expf(logit - mx) : 0.f;
    float es = blockReduceSum(e, red);
    if (act) alpha[tid] = e / es;
    __syncthreads();

    const float* S_t = Sall + ((size_t)BB + b) * L * L;
    const float* ent = entall + (size_t)b * L;
    const int warp = tid >> 5, lane = tid & 31;
    float acc = 0.f;
    for (int t = warp; t < L; t += 8) {
        const float* St = S_t + (size_t)t * L;
        float cr = 0.f;
        for (int k = lane; k < L; k += 32) cr = fmaf(St[k], lsrow[k], cr);
        #pragma unroll
        for (int o = 16; o; o >>= 1) cr += __shfl_down_sync(0xffffffffu, cr, o);
        if (lane == 0) acc = fmaf(alpha[t], ent[t] - cr, acc);
    }
    float total = blockReduceSum(acc, red);
    if (tid == 0) atomicAdd(out, total * inv_denom);
}

// ---------------- launch ----------------
extern "C" void kernel_launch(void* const* d_in, const int* in_sizes, int n_in,
                              void* d_out, int out_size) {
    const float* fs  = (const float*)d_in[0];
    const float* ft  = (const float*)d_in[1];
    const float* WqT = (const float*)d_in[2];
    const float* bqT = (const float*)d_in[3];
    const float* gqT = (const float*)d_in[4];
    const float* BqT = (const float*)d_in[5];
    const float* WkT = (const float*)d_in[6];
    const float* bkT = (const float*)d_in[7];
    const float* gkT = (const float*)d_in[8];
    const float* BkT = (const float*)d_in[9];
    const float* WqF = (const float*)d_in[10];
    const float* bqF = (const float*)d_in[11];
    const float* gqF = (const float*)d_in[12];
    const float* BqF = (const float*)d_in[13];
    const float* WkF = (const float*)d_in[14];
    const float* bkF = (const float*)d_in[15];
    const float* gkF = (const float*)d_in[16];
    const float* BkF = (const float*)d_in[17];
    float* out = (float*)d_out;

    void *pGT, *pGF, *pST, *pLST, *pSF, *pLSF, *pmT, *pmF, *pentT, *pentF;
    cudaGetSymbolAddress(&pGT, g_GT);
    cudaGetSymbolAddress(&pGF, g_GF);
    cudaGetSymbolAddress(&pST, g_ST);
    cudaGetSymbolAddress(&pLST, g_LST);
    cudaGetSymbolAddress(&pSF, g_SF);
    cudaGetSymbolAddress(&pLSF, g_LSF);
    cudaGetSymbolAddress(&pmT, g_mT);
    cudaGetSymbolAddress(&pmF, g_mF);
    cudaGetSymbolAddress(&pentT, g_entT);
    cudaGetSymbolAddress(&pentF, g_entF);

    cudaMemsetAsync(pGT, 0, sizeof(float) * 2 * BB * LT * LT, 0);
    cudaMemsetAsync(pGF, 0, sizeof(float) * 2 * BB * LF * LF, 0);
    cudaMemsetAsync(d_out, 0, sizeof(float) * (size_t)out_size, 0);

    gram_time_kernel<<<dim3(6 * CSPLIT_T, BB, 2), 256>>>(fs, ft);
    gram_freq_kernel<<<dim3(3 * CSPLIT_F, BB, 2), 256>>>(fs, ft);

    postproc_kernel<<<dim3(LT, BB, 2), 256>>>((const float*)pGT, (float*)pST,
                                              (float*)pLST, (float*)pmT,
                                              (float*)pentT, LT);
    postproc_kernel<<<dim3(LF, BB, 2), 256>>>((const float*)pGF, (float*)pSF,
                                              (float*)pLSF, (float*)pmF,
                                              (float*)pentF, LF);

    const float invdT = 1.0f / ((float)(BB * LT * LT) + 1e-8f);
    const float invdF = 1.0f / ((float)(BB * LF * LF) + 1e-8f);
    loss_kernel<<<dim3(LT, BB), 256>>>((const float*)pST, (const float*)pLST,
                                       (const float*)pmT, (const float*)pentT,
                                       WqT, bqT, gqT, BqT, WkT, bkT, gkT, BkT,
                                       out, LT, invdT);
    loss_kernel<<<dim3(LF, BB), 256>>>((const float*)pSF, (const float*)pLSF,
                                       (const float*)pmF, (const float*)pentF,
                                       WqF, bqF, gqF, BqF, WkF, bkF, gkF, BkF,
                                       out, LF, invdF);
}

// round 16
// speedup vs baseline: 1.2534x; 1.2534x over previous
#include <cuda_runtime.h>
#include <cuda_bf16.h>
#include <mma.h>
#include <math.h>
#include <stdint.h>

using namespace nvcuda;

#define BB 8
#define CC 64
#define TT 192
#define FF 128
#define LT 192
#define LF 128
#define CSPLIT_T 8   // 8 channels per CTA (time) -> K=1024
#define CSPLIT_F 16  // 4 channels per CTA (freq) -> K=768
#define APITCH 40    // bf16 pitch (80B, multiple of 16B)
#define CPITCH 68    // f32 pitch for C staging

// ---------------- scratch ----------------
__device__ float g_GT [2 * BB * LT * LT];
__device__ float g_GF [2 * BB * LF * LF];
__device__ float g_ST [2 * BB * LT * LT];
__device__ float g_LST[2 * BB * LT * LT];
__device__ float g_SF [2 * BB * LF * LF];
__device__ float g_LSF[2 * BB * LF * LF];
__device__ float g_mT [2 * BB * LT];
__device__ float g_mF [2 * BB * LF];
__device__ float g_entT[BB * LT];
__device__ float g_entF[BB * LF];

// split one float4 into bf16 hi + bf16 lo (residual)
__device__ __forceinline__ void cvt4(const float4 v, __nv_bfloat16* hp, __nv_bfloat16* lp) {
    __nv_bfloat162 h01 = __floats2bfloat162_rn(v.x, v.y);
    __nv_bfloat162 h23 = __floats2bfloat162_rn(v.z, v.w);
    __nv_bfloat162 l01 = __floats2bfloat162_rn(v.x - __bfloat162float(h01.x),
                                               v.y - __bfloat162float(h01.y));
    __nv_bfloat162 l23 = __floats2bfloat162_rn(v.z - __bfloat162float(h23.x),
                                               v.w - __bfloat162float(h23.y));
    *(__nv_bfloat162*)(hp)     = h01;
    *(__nv_bfloat162*)(hp + 2) = h23;
    *(__nv_bfloat162*)(lp)     = l01;
    *(__nv_bfloat162*)(lp + 2) = l23;
}

typedef wmma::fragment<wmma::matrix_a, 16, 16, 16, __nv_bfloat16, wmma::row_major> FragA;
typedef wmma::fragment<wmma::matrix_b, 16, 16, 16, __nv_bfloat16, wmma::col_major> FragB;
typedef wmma::fragment<wmma::accumulator, 16, 16, 16, float> FragC;

// ---------------- gram: time view (wmma bf16-split) ----------------
// G[b,i,j] = sum_{c,f} X[c,i,f]*X[c,j,f]; 3x3 tile-pairs of 64, split-K over channels.
__global__ __launch_bounds__(256)
void gram_time_kernel(const float* __restrict__ fs, const float* __restrict__ ft) {
    const int pair = blockIdx.x % 6;
    const int cs   = blockIdx.x / 6;
    const int b    = blockIdx.y;
    const int z    = blockIdx.z;
    const int PI[6] = {0, 0, 0, 1, 1, 2};
    const int PJ[6] = {0, 1, 2, 1, 2, 2};
    const int ti = PI[pair], tj = PJ[pair];
    const float* X = (z == 0 ? fs : ft) + (size_t)b * CC * TT * FF;

    __shared__ __align__(16) __nv_bfloat16 Ah[64][APITCH], Al[64][APITCH];
    __shared__ __align__(16) __nv_bfloat16 Bh[64][APITCH], Bl[64][APITCH];
    __shared__ __align__(16) float Cs[64][CPITCH];

    const int tid = threadIdx.x;
    const int warp = tid >> 5;
    const int wm  = warp >> 1;        // m block 0..3 (16 rows each)
    const int wn0 = (warp & 1) * 2;   // n blocks wn0, wn0+1

    FragC c[2];
    wmma::fill_fragment(c[0], 0.0f);
    wmma::fill_fragment(c[1], 0.0f);

    const int c0 = cs * (CC / CSPLIT_T);
    const int r0  = tid >> 2;          // 0..63
    const int fc4 = (tid & 3) * 8;     // 0,8,16,24

    for (int cc = c0; cc < c0 + CC / CSPLIT_T; ++cc) {
        const float* baseA = X + (size_t)cc * TT * FF + (size_t)(ti * 64) * FF;
        const float* baseB = X + (size_t)cc * TT * FF + (size_t)(tj * 64) * FF;
        for (int f0 = 0; f0 < FF; f0 += 32) {
            #pragma unroll
            for (int h = 0; h < 8; h += 4) {
                float4 va = *(const float4*)(baseA + (size_t)r0 * FF + f0 + fc4 + h);
                cvt4(va, &Ah[r0][fc4 + h], &Al[r0][fc4 + h]);
                float4 vb = *(const float4*)(baseB + (size_t)r0 * FF + f0 + fc4 + h);
                cvt4(vb, &Bh[r0][fc4 + h], &Bl[r0][fc4 + h]);
            }
            __syncthreads();
            #pragma unroll
            for (int kk = 0; kk < 32; kk += 16) {
                FragA ah, al;
                wmma::load_matrix_sync(ah, &Ah[wm * 16][kk], APITCH);
                wmma::load_matrix_sync(al, &Al[wm * 16][kk], APITCH);
                #pragma unroll
                for (int j = 0; j < 2; ++j) {
                    FragB bh, bl;
                    wmma::load_matrix_sync(bh, &Bh[(wn0 + j) * 16][kk], APITCH);
                    wmma::load_matrix_sync(bl, &Bl[(wn0 + j) * 16][kk], APITCH);
                    wmma::mma_sync(c[j], ah, bh, c[j]);
                    wmma::mma_sync(c[j], ah, bl, c[j]);
                    wmma::mma_sync(c[j], al, bh, c[j]);
                }
            }
            __syncthreads();
        }
    }

    wmma::store_matrix_sync(&Cs[wm * 16][(wn0 + 0) * 16], c[0], CPITCH, wmma::mem_row_major);
    wmma::store_matrix_sync(&Cs[wm * 16][(wn0 + 1) * 16], c[1], CPITCH, wmma::mem_row_major);
    __syncthreads();

    float* G = g_GT + ((size_t)z * BB + b) * LT * LT;
    for (int e = tid; e < 64 * 64; e += 256) {
        int i = e >> 6, j = e & 63;
        float v = Cs[i][j];
        int gi = ti * 64 + i, gj = tj * 64 + j;
        atomicAdd(&G[(size_t)gi * LT + gj], v);
        if (ti != tj) atomicAdd(&G[(size_t)gj * LT + gi], v);
    }
}

// ---------------- gram: freq view (wmma bf16-split) ----------------
// G[b,f1,f2] = sum_{c,t} X[c,t,f1]*X[c,t,f2]; 2x2 tile-pairs of 64.
__global__ __launch_bounds__(256)
void gram_freq_kernel(const float* __restrict__ fs, const float* __restrict__ ft) {
    const int pair = blockIdx.x % 3;
    const int cs   = blockIdx.x / 3;
    const int b    = blockIdx.y;
    const int z    = blockIdx.z;
    const int PI[3] = {0, 0, 1};
    const int PJ[3] = {0, 1, 1};
    const int ti = PI[pair], tj = PJ[pair];
    const float* X = (z == 0 ? fs : ft) + (size_t)b * CC * TT * FF;

    __shared__ __align__(16) __nv_bfloat16 Ah[64][APITCH], Al[64][APITCH];
    __shared__ __align__(16) __nv_bfloat16 Bh[64][APITCH], Bl[64][APITCH];
    __shared__ __align__(16) float Cs[64][CPITCH];

    const int tid = threadIdx.x;
    const int warp = tid >> 5;
    const int wm  = warp >> 1;
    const int wn0 = (warp & 1) * 2;

    FragC c[2];
    wmma::fill_fragment(c[0], 0.0f);
    wmma::fill_fragment(c[1], 0.0f);

    const int c0 = cs * (CC / CSPLIT_F);
    const int lf  = tid & 63;   // f within tile (coalesced global)
    const int ltg = tid >> 6;   // 0..3

    for (int cc = c0; cc < c0 + CC / CSPLIT_F; ++cc) {
        const float* base = X + (size_t)cc * TT * FF;
        for (int t0 = 0; t0 < TT; t0 += 32) {
            #pragma unroll
            for (int it = 0; it < 8; ++it) {
                const int kt = ltg + it * 4;
                float va = base[(size_t)(t0 + kt) * FF + ti * 64 + lf];
                float vb = base[(size_t)(t0 + kt) * FF + tj * 64 + lf];
                __nv_bfloat16 ahv = __float2bfloat16_rn(va);
                __nv_bfloat16 bhv = __float2bfloat16_rn(vb);
                Ah[lf][kt] = ahv;
                Al[lf][kt] = __float2bfloat16_rn(va - __bfloat162float(ahv));
                Bh[lf][kt] = bhv;
                Bl[lf][kt] = __float2bfloat16_rn(vb - __bfloat162float(bhv));
            }
            __syncthreads();
            #pragma unroll
            for (int kk = 0; kk < 32; kk += 16) {
                FragA ah, al;
                wmma::load_matrix_sync(ah, &Ah[wm * 16][kk], APITCH);
                wmma::load_matrix_sync(al, &Al[wm * 16][kk], APITCH);
                #pragma unroll
                for (int j = 0; j < 2; ++j) {
                    FragB bh, bl;
                    wmma::load_matrix_sync(bh, &Bh[(wn0 + j) * 16][kk], APITCH);
                    wmma::load_matrix_sync(bl, &Bl[(wn0 + j) * 16][kk], APITCH);
                    wmma::mma_sync(c[j], ah, bh, c[j]);
                    wmma::mma_sync(c[j], ah, bl, c[j]);
                    wmma::mma_sync(c[j], al, bh, c[j]);
                }
            }
            __syncthreads();
        }
    }

    wmma::store_matrix_sync(&Cs[wm * 16][(wn0 + 0) * 16], c[0], CPITCH, wmma::mem_row_major);
    wmma::store_matrix_sync(&Cs[wm * 16][(wn0 + 1) * 16], c[1], CPITCH, wmma::mem_row_major);
    __syncthreads();

    float* G = g_GF + ((size_t)z * BB + b) * LF * LF;
    for (int e = tid; e < 64 * 64; e += 256) {
        int i = e >> 6, j = e & 63;
        float v = Cs[i][j];
        int gi = ti * 64 + i, gj = tj * 64 + j;
        atomicAdd(&G[(size_t)gi * LF + gj], v);
        if (ti != tj) atomicAdd(&G[(size_t)gj * LF + gi], v);
    }
}

// ---------------- reductions / mlp ----------------
__device__ __forceinline__ float blockReduceSum(float v, float* sh) {
    int tid = threadIdx.x;
    sh[tid] = v; __syncthreads();
    #pragma unroll
    for (int s = 128; s > 0; s >>= 1) {
        if (tid < s) sh[tid] += sh[tid + s];
        __syncthreads();
    }
    float r = sh[0]; __syncthreads();
    return r;
}
__device__ __forceinline__ float blockReduceMax(float v, float* sh) {
    int tid = threadIdx.x;
    sh[tid] = v; __syncthreads();
    #pragma unroll
    for (int s = 128; s > 0; s >>= 1) {
        if (tid < s) sh[tid] = fmaxf(sh[tid], sh[tid + s]);
        __syncthreads();
    }
    float r = sh[0]; __syncthreads();
    return r;
}
__device__ __forceinline__ void mlp4(float x, const float* __restrict__ W,
                                     const float* __restrict__ b,
                                     const float* __restrict__ g,
                                     const float* __restrict__ be, float* o) {
    float h[4];
    float mu = 0.f;
    #pragma unroll
    for (int i = 0; i < 4; ++i) {
        h[i] = fmaxf(fmaf(W[i], x, b[i]), 0.f);
        mu += h[i];
    }
    mu *= 0.25f;
    float var = 0.f;
    #pragma unroll
    for (int i = 0; i < 4; ++i) {
        float d = h[i] - mu;
        var = fmaf(d, d, var);
    }
    var *= 0.25f;
    float inv = rsqrtf(var + 1e-5f);
    #pragma unroll
    for (int i = 0; i < 4; ++i)
        o[i] = fmaf(g[i], (h[i] - mu) * inv, be[i]);
}

// ---------------- postprocess ----------------
__global__ __launch_bounds__(256)
void postproc_kernel(const float* __restrict__ Gall, float* __restrict__ Sall,
                     float* __restrict__ LSall, float* __restrict__ mall,
                     float* __restrict__ entall, int L) {
    const int row = blockIdx.x, b = blockIdx.y, z = blockIdx.z;
    const float* G = Gall + ((size_t)z * BB + b) * L * L;
    __shared__ float red[256];
    const int j = threadIdx.x;
    const bool act = j < L;

    float P = 0.f;
    if (act) {
        float invn_j = 1.f / fmaxf(sqrtf(G[(size_t)j * L + j]), 1e-8f);
        float invn_i = 1.f / fmaxf(sqrtf(G[(size_t)row * L + row]), 1e-8f);
        P = fmaf(G[(size_t)row * L + j] * invn_i * invn_j, 0.5f, 0.5f);
    }
    float msum = blockReduceSum(act ? P : 0.f, red);
    if (j == 0) mall[((size_t)z * BB + b) * L + row] = msum / (float)L;

    float mx = blockReduceMax(act ? P : -3.4e38f, red);
    float e = act ? expf(P - mx) : 0.f;
    float es = blockReduceSum(e, red);
    float S  = e / es + 1e-8f;
    float LSv = logf(S + 1e-8f);
    if (act) {
        size_t o = ((size_t)z * BB + b) * L * L + (size_t)row * L + j;
        Sall[o]  = S;
        LSall[o] = LSv;
    }
    if (z == 1) {
        float ev = blockReduceSum(act ? S * LSv : 0.f, red);
        if (j == 0) entall[(size_t)b * L + row] = ev;
    }
}

// ---------------- alpha + KL + loss ----------------
__global__ __launch_bounds__(256)
void loss_kernel(const float* __restrict__ Sall, const float* __restrict__ LSall,
                 const float* __restrict__ mall, const float* __restrict__ entall,
                 const float* __restrict__ Wq, const float* __restrict__ bq,
                 const float* __restrict__ gq, const float* __restrict__ Bq,
                 const float* __restrict__ Wk, const float* __restrict__ bk,
                 const float* __restrict__ gk, const float* __restrict__ Bk,
                 float* __restrict__ out, int L, float inv_denom) {
    const int s = blockIdx.x, b = blockIdx.y;
    __shared__ float red[256];
    __shared__ float kv[192 * 4];
    __shared__ float alpha[192];
    __shared__ float lsrow[192];
    const int tid = threadIdx.x;
    const bool act = tid < L;

    const float* m_s = mall + (size_t)b * L;
    const float* m_t = mall + ((size_t)BB + b) * L;

    if (act) {
        float kk4[4];
        mlp4(m_t[tid], Wk, bk, gk, Bk, kk4);
        #pragma unroll
        for (int h = 0; h < 4; ++h) kv[tid * 4 + h] = kk4[h];
        lsrow[tid] = LSall[(size_t)b * L * L + (size_t)s * L + tid];
    }
    float q[4];
    mlp4(m_s[s], Wq, bq, gq, Bq, q);
    __syncthreads();

    const float inv_scale = 1.f / sqrtf(4.0f + 1e-8f);
    float logit = -3.4e38f;
    if (act) {
        float d = q[0] * kv[tid * 4 + 0] + q[1] * kv[tid * 4 + 1] +
                  q[2] * kv[tid * 4 + 2] + q[3] * kv[tid * 4 + 3];
        logit = d * inv_scale;
    }
    float mx = blockReduceMax(logit, red);
    float e = act ? expf(logit - mx) : 0.f;
    float es = blockReduceSum(e, red);
    if (act) alpha[tid] = e / es;
    __syncthreads();

    const float* S_t = Sall + ((size_t)BB + b) * L * L;
    const float* ent = entall + (size_t)b * L;
    const int warp = tid >> 5, lane = tid & 31;
    float acc = 0.f;
    for (int t = warp; t < L; t += 8) {
        const float* St = S_t + (size_t)t * L;
        float cr = 0.f;
        for (int k = lane; k < L; k += 32) cr = fmaf(St[k], lsrow[k], cr);
        #pragma unroll
        for (int o = 16; o; o >>= 1) cr += __shfl_down_sync(0xffffffffu, cr, o);
        if (lane == 0) acc = fmaf(alpha[t], ent[t] - cr, acc);
    }
    float total = blockReduceSum(acc, red);
    if (tid == 0) atomicAdd(out, total * inv_denom);
}

// ---------------- launch ----------------
extern "C" void kernel_launch(void* const* d_in, const int* in_sizes, int n_in,
                              void* d_out, int out_size) {
    const float* fs  = (const float*)d_in[0];
    const float* ft  = (const float*)d_in[1];
    const float* WqT = (const float*)d_in[2];
    const float* bqT = (const float*)d_in[3];
    const float* gqT = (const float*)d_in[4];
    const float* BqT = (const float*)d_in[5];
    const float* WkT = (const float*)d_in[6];
    const float* bkT = (const float*)d_in[7];
    const float* gkT = (const float*)d_in[8];
    const float* BkT = (const float*)d_in[9];
    const float* WqF = (const float*)d_in[10];
    const float* bqF = (const float*)d_in[11];
    const float* gqF = (const float*)d_in[12];
    const float* BqF = (const float*)d_in[13];
    const float* WkF = (const float*)d_in[14];
    const float* bkF = (const float*)d_in[15];
    const float* gkF = (const float*)d_in[16];
    const float* BkF = (const float*)d_in[17];
    float* out = (float*)d_out;

    void *pGT, *pGF, *pST, *pLST, *pSF, *pLSF, *pmT, *pmF, *pentT, *pentF;
    cudaGetSymbolAddress(&pGT, g_GT);
    cudaGetSymbolAddress(&pGF, g_GF);
    cudaGetSymbolAddress(&pST, g_ST);
    cudaGetSymbolAddress(&pLST, g_LST);
    cudaGetSymbolAddress(&pSF, g_SF);
    cudaGetSymbolAddress(&pLSF, g_LSF);
    cudaGetSymbolAddress(&pmT, g_mT);
    cudaGetSymbolAddress(&pmF, g_mF);
    cudaGetSymbolAddress(&pentT, g_entT);
    cudaGetSymbolAddress(&pentF, g_entF);

    cudaMemsetAsync(pGT, 0, sizeof(float) * 2 * BB * LT * LT, 0);
    cudaMemsetAsync(pGF, 0, sizeof(float) * 2 * BB * LF * LF, 0);
    cudaMemsetAsync(d_out, 0, sizeof(float) * (size_t)out_size, 0);

    gram_time_kernel<<<dim3(6 * CSPLIT_T, BB, 2), 256>>>(fs, ft);
    gram_freq_kernel<<<dim3(3 * CSPLIT_F, BB, 2), 256>>>(fs, ft);

    postproc_kernel<<<dim3(LT, BB, 2), 256>>>((const float*)pGT, (float*)pST,
                                              (float*)pLST, (float*)pmT,
                                              (float*)pentT, LT);
    postproc_kernel<<<dim3(LF, BB, 2), 256>>>((const float*)pGF, (float*)pSF,
                                              (float*)pLSF, (float*)pmF,
                                              (float*)pentF, LF);

    const float invdT = 1.0f / ((float)(BB * LT * LT) + 1e-8f);
    const float invdF = 1.0f / ((float)(BB * LF * LF) + 1e-8f);
    loss_kernel<<<dim3(LT, BB), 256>>>((const float*)pST, (const float*)pLST,
                                       (const float*)pmT, (const float*)pentT,
                                       WqT, bqT, gqT, BqT, WkT, bkT, gkT, BkT,
                                       out, LT, invdT);
    loss_kernel<<<dim3(LF, BB), 256>>>((const float*)pSF, (const float*)pLSF,
                                       (const float*)pmF, (const float*)pentF,
                                       WqF, bqF, gqF, BqF, WkF, bkF, gkF, BkF,
                                       out, LF, invdF);
}